// round 15
// baseline (speedup 1.0000x reference)
#include <cuda_runtime.h>
#include <cuda_bf16.h>
#include <float.h>

// Problem constants
#define B_   16
#define N_   2048
#define C_   128
#define M_   (B_ * N_)          // 32768 rows
#define KNN  8
#define NBLK 4

#define ALPHA_F    0.8888888888888888f   // 8/9
#define ONEMA_F    0.1111111111111111f   // 1/9
#define WEDGE_F    0.125f                // normalized adjacency entry (deg=8 everywhere)
#define COEF_F     0.013888888888888888f // ONEMA*WEDGE = 1/72

typedef unsigned long long u64;
typedef unsigned int u32;

// ---------------- scratch (static device globals; no allocs allowed) ---------
__device__ float g_pts[M_ * C_];
__device__ float g_Ya [2][M_ * C_];   // ping-pong: pts + alpha*relu(pts)@WcT
__device__ float g_Yg [2][M_ * C_];   // ping-pong: pts@WgT
__device__ float g_Uc [M_ * 6];
__device__ float g_Ug [M_ * 6];
__device__ int   g_nbr[M_ * KNN];  // [0]=self, [1..7]=kNN (within-batch indices)
// precomputed bf16 splits of Wc/Wg: [mat][blk][128*128]
__device__ __nv_bfloat16 g_Wsh[2 * NBLK * C_ * C_];
__device__ __nv_bfloat16 g_Wsl[2 * NBLK * C_ * C_];

// ======================= helpers =============================================
__device__ __forceinline__ u32 smem_u32(const void* p) {
    u32 a;
    asm("{ .reg .u64 t; cvta.to.shared.u64 t, %1; cvt.u32.u64 %0, t; }"
        : "=r"(a) : "l"(p));
    return a;
}
__device__ __forceinline__ float bfhi(float x) {
    return __bfloat162float(__float2bfloat16_rn(x));
}
__device__ __forceinline__ u32 packbf(float lo, float hi) {
    u32 r; asm("cvt.rn.bf16x2.f32 %0, %1, %2;" : "=r"(r) : "f"(hi), "f"(lo));
    return r;
}
__device__ __forceinline__ void ldsm_x4(u32 r[4], u32 addr) {
    asm volatile("ldmatrix.sync.aligned.m8n8.x4.shared.b16 {%0,%1,%2,%3}, [%4];"
        : "=r"(r[0]), "=r"(r[1]), "=r"(r[2]), "=r"(r[3]) : "r"(addr));
}
__device__ __forceinline__ void mma16816(float c[4], const u32 a[4], const u32 b[2]) {
    asm volatile("mma.sync.aligned.m16n8k16.row.col.f32.bf16.bf16.f32 "
        "{%0,%1,%2,%3}, {%4,%5,%6,%7}, {%8,%9}, {%0,%1,%2,%3};"
        : "+f"(c[0]), "+f"(c[1]), "+f"(c[2]), "+f"(c[3])
        : "r"(a[0]), "r"(a[1]), "r"(a[2]), "r"(a[3]), "r"(b[0]), "r"(b[1]));
}

// HMMA smem layout (bf16, padded stride 136; 128-row A tile, 128-row W tile)
#define LDB  136
#define REGB (C_ * LDB * 2)               // 34816 per bf16 region
#define HA_H 0
#define HA_L REGB
#define HW_H (2 * REGB)
#define HW_L (3 * REGB)
#define PTS_OFF (4 * REGB)                // fp32 pts tile [128][132]
#define LDP  132
#define GEMM_SMEM (PTS_OFF + 128 * LDP * 4)   // 139264 + 67584 = 206848

// ---------------- 1) kNN top-8 + Wc/Wg bf16 split prep -----------------------
__global__ void knn_kernel(const float* __restrict__ xyz,
                           const float* __restrict__ Wc,
                           const float* __restrict__ Wg) {
    __shared__ float4 sP[N_];   // (x, y, z, |p|^2) interleaved -> 1 LDS.128/cand
    {
        int gt = blockIdx.x * 256 + threadIdx.x;
        for (int i = gt; i < NBLK * C_ * C_; i += 128 * 256) {
            float w = Wc[i];
            float h = bfhi(w);
            g_Wsh[i] = __float2bfloat16_rn(h);
            g_Wsl[i] = __float2bfloat16_rn(w - h);
            float w2 = Wg[i];
            float h2 = bfhi(w2);
            g_Wsh[NBLK * C_ * C_ + i] = __float2bfloat16_rn(h2);
            g_Wsl[NBLK * C_ * C_ + i] = __float2bfloat16_rn(w2 - h2);
        }
    }
    int b = blockIdx.x >> 3;
    int qBase = (blockIdx.x & 7) * 256;
    const float* X = xyz + (size_t)b * 3 * N_;
    for (int i = threadIdx.x; i < N_; i += 256) {
        float x = X[i], y = X[N_ + i], z = X[2 * N_ + i];
        sP[i] = make_float4(x, y, z, x * x + y * y + z * z);
    }
    __syncthreads();

    int q = qBase + threadIdx.x;
    float4 qp = sP[q];
    float bd[KNN]; int bi[KNN];
#pragma unroll
    for (int s = 0; s < KNN; ++s) { bd[s] = FLT_MAX; bi[s] = 0x7fffffff; }

    for (int j = 0; j < N_; ++j) {
        float4 pj = sP[j];
        float inner = qp.x * pj.x + qp.y * pj.y + qp.z * pj.z;
        float d = (qp.w + pj.w) - 2.0f * inner;
        if (d < bd[KNN - 1]) {                   // strict <: stable tie (lower idx wins)
            bd[KNN - 1] = d; bi[KNN - 1] = j;
#pragma unroll
            for (int s = KNN - 1; s > 0; --s) {
                if (bd[s] < bd[s - 1]) {
                    float td = bd[s]; bd[s] = bd[s - 1]; bd[s - 1] = td;
                    int   ti = bi[s]; bi[s] = bi[s - 1]; bi[s - 1] = ti;
                }
            }
        }
    }
    int* outp = g_nbr + (size_t)(b * N_ + q) * KNN;
    outp[0] = q;
#pragma unroll
    for (int s = 1; s < KNN; ++s) outp[s] = bi[s];
}

// ------- 2) transpose points (B,C,N) -> pts (B,N,C) --------------------------
__global__ void transpose_in(const float* __restrict__ pin) {
    __shared__ float tile[32][33];
    int b = blockIdx.z;
    int n0 = blockIdx.x * 32, c0 = blockIdx.y * 32;
    const float* src = pin + (size_t)b * C_ * N_;
    float* dst = g_pts + (size_t)b * N_ * C_;
    for (int r = threadIdx.y; r < 32; r += 8)
        tile[r][threadIdx.x] = src[(c0 + r) * N_ + n0 + threadIdx.x];
    __syncthreads();
    for (int r = threadIdx.y; r < 32; r += 8)
        dst[(n0 + r) * C_ + c0 + threadIdx.x] = tile[threadIdx.x][r];
}

// ---------------- 3) HMMA GEMM with fused neighbor-gather A-load -------------
// grid (256, 2). y=0: Ya[wr] = pts_i + ALPHA*(relu(pts_i)@WcT); y=1: Yg[wr] = pts_i@WgT.
// fused=0 (block 0): pts_0 = g_pts.  fused=1 (blocks 1..3):
//   pts_i = Ya[rd] + (1/72)*sum_8 Yg[rd][nbr]   computed in the loader.
// rd != wr (ping-pong) so no launch reads a buffer it writes -> race-free.
// fp32 pts tile kept in smem for the mat-0 residual epilogue.
// MMA order is stage-major (all hh, all lh, all hl) to separate same-acc deps.
__global__ __launch_bounds__(256) void gemm_tc(int blk, int fused, int rd, int wr) {
    extern __shared__ char S[];
    int t = threadIdx.x;
    int wid = t >> 5, lane = t & 31;
    const int mat = blockIdx.y;               // 0 = Wc/relu path, 1 = Wg
    const bool doRelu = (mat == 0);
    int row0 = blockIdx.x * 128;
    u32 sb = smem_u32(S);
    float* sPts = (float*)(S + PTS_OFF);
    const float* YaR = g_Ya[rd];
    const float* YgR = g_Yg[rd];
    float* YaW = g_Ya[wr];
    float* YgW = g_Yg[wr];

    // ---- A tile: 128 rows x 128 ch; 2 threads/row, 64 ch (half) each --------
    {
        int row = t >> 1, half = t & 1;
        int node = row0 + row;
        int bbase = node & ~(N_ - 1);
        int4 nbA = make_int4(0, 0, 0, 0), nbB = nbA;
        if (fused) {
            nbA = *(const int4*)&g_nbr[(size_t)node * KNN];
            nbB = *(const int4*)&g_nbr[(size_t)node * KNN + 4];
        }
        int nbs[8] = {nbA.x, nbA.y, nbA.z, nbA.w, nbB.x, nbB.y, nbB.z, nbB.w};
#pragma unroll
        for (int pass = 0; pass < 4; ++pass) {
            int c = half * 64 + pass * 16;    // 16 ch per pass
            float4 v[4];
            if (!fused) {
#pragma unroll
                for (int q = 0; q < 4; ++q)
                    v[q] = *(const float4*)&g_pts[(size_t)node * C_ + c + q * 4];
            } else {
                float4 sm[4];
#pragma unroll
                for (int q = 0; q < 4; ++q) {
                    v[q] = *(const float4*)&YaR[(size_t)node * C_ + c + q * 4];
                    sm[q] = make_float4(0.f, 0.f, 0.f, 0.f);
                }
#pragma unroll
                for (int s = 0; s < 8; ++s) {
                    const float* yr = &YgR[(size_t)(bbase + nbs[s]) * C_ + c];
#pragma unroll
                    for (int q = 0; q < 4; ++q) {
                        float4 y = *(const float4*)&yr[q * 4];
                        sm[q].x += y.x; sm[q].y += y.y;
                        sm[q].z += y.z; sm[q].w += y.w;
                    }
                }
#pragma unroll
                for (int q = 0; q < 4; ++q) {
                    v[q].x += COEF_F * sm[q].x; v[q].y += COEF_F * sm[q].y;
                    v[q].z += COEF_F * sm[q].z; v[q].w += COEF_F * sm[q].w;
                }
            }
#pragma unroll
            for (int q = 0; q < 4; ++q) {
                int cpos = c + q * 4;
                *(float4*)&sPts[row * LDP + cpos] = v[q];   // fp32 tile for epilogue
                float4 w = v[q];
                if (doRelu) {
                    w.x = fmaxf(w.x, 0.f); w.y = fmaxf(w.y, 0.f);
                    w.z = fmaxf(w.z, 0.f); w.w = fmaxf(w.w, 0.f);
                }
                float h0 = bfhi(w.x), h1 = bfhi(w.y), h2 = bfhi(w.z), h3 = bfhi(w.w);
                u32 so = (u32)(row * LDB + cpos) * 2;
                *(u64*)(S + HA_H + so) =
                    (u64)packbf(h0, h1) | ((u64)packbf(h2, h3) << 32);
                *(u64*)(S + HA_L + so) =
                    (u64)packbf(w.x - h0, w.y - h1) | ((u64)packbf(w.z - h2, w.w - h3) << 32);
            }
        }
    }
    // ---- W tile: precomputed bf16 hi/lo -------------------------------------
    {
        int wrow = t >> 1, half = t & 1;
        size_t gb = (size_t)(mat * NBLK + blk) * (C_ * C_) + wrow * C_ + half * 64;
        const uint4* wh = (const uint4*)&g_Wsh[gb];
        const uint4* wl = (const uint4*)&g_Wsl[gb];
        u32 wo = (u32)(wrow * LDB + half * 64) * 2;
#pragma unroll
        for (int j = 0; j < 8; ++j) {
            *(uint4*)(S + HW_H + wo + j * 16) = wh[j];
            *(uint4*)(S + HW_L + wo + j * 16) = wl[j];
        }
    }
    __syncthreads();

    int wm = wid & 3, wn = wid >> 2;          // warp tile 32 rows x 64 cols
    int gid = lane >> 2, tig = lane & 3;
    int arow = (lane & 7) + ((lane >> 3) & 1) * 8;
    int acol = ((lane >> 4) & 1) * 8;
    int brow = (lane & 7) + ((lane >> 4) & 1) * 8;
    int bcol = ((lane >> 3) & 1) * 8;

    u32 aAh[2], aAl[2];
#pragma unroll
    for (int mt = 0; mt < 2; ++mt) {
        u32 o = (u32)((wm * 32 + mt * 16 + arow) * LDB + acol) * 2;
        aAh[mt] = sb + HA_H + o;
        aAl[mt] = sb + HA_L + o;
    }
    u32 aBh[4], aBl[4];
#pragma unroll
    for (int p = 0; p < 4; ++p) {
        u32 o = (u32)((wn * 64 + p * 16 + brow) * LDB + bcol) * 2;
        aBh[p] = sb + HW_H + o;
        aBl[p] = sb + HW_L + o;
    }

    float acc[2][8][4];
#pragma unroll
    for (int i = 0; i < 2; ++i)
#pragma unroll
        for (int j = 0; j < 8; ++j)
#pragma unroll
            for (int q = 0; q < 4; ++q) acc[i][j][q] = 0.f;

    for (int kt = 0; kt < 8; ++kt) {
        u32 kadd = kt * 32;
        u32 ah0[4], ah1[4], al0[4], al1[4];
        ldsm_x4(ah0, aAh[0] + kadd); ldsm_x4(ah1, aAh[1] + kadd);
        ldsm_x4(al0, aAl[0] + kadd); ldsm_x4(al1, aAl[1] + kadd);
        u32 bh[4][4];
#pragma unroll
        for (int p = 0; p < 4; ++p) ldsm_x4(bh[p], aBh[p] + kadd);
        // stage hh: 16 independent-acc MMAs
#pragma unroll
        for (int p = 0; p < 4; ++p) {
            mma16816(acc[0][2 * p],     ah0, bh[p]);
            mma16816(acc[0][2 * p + 1], ah0, bh[p] + 2);
            mma16816(acc[1][2 * p],     ah1, bh[p]);
            mma16816(acc[1][2 * p + 1], ah1, bh[p] + 2);
        }
        u32 bl[4][4];
#pragma unroll
        for (int p = 0; p < 4; ++p) ldsm_x4(bl[p], aBl[p] + kadd);
        // stage lh
#pragma unroll
        for (int p = 0; p < 4; ++p) {
            mma16816(acc[0][2 * p],     al0, bh[p]);
            mma16816(acc[0][2 * p + 1], al0, bh[p] + 2);
            mma16816(acc[1][2 * p],     al1, bh[p]);
            mma16816(acc[1][2 * p + 1], al1, bh[p] + 2);
        }
        // stage hl
#pragma unroll
        for (int p = 0; p < 4; ++p) {
            mma16816(acc[0][2 * p],     ah0, bl[p]);
            mma16816(acc[0][2 * p + 1], ah0, bl[p] + 2);
            mma16816(acc[1][2 * p],     ah1, bl[p]);
            mma16816(acc[1][2 * p + 1], ah1, bl[p] + 2);
        }
    }

    // ---- epilogue: c0,c1 -> (row, cc..+1); c2,c3 -> (row+8, cc..+1) ---------
#pragma unroll
    for (int mt = 0; mt < 2; ++mt) {
#pragma unroll
        for (int nt = 0; nt < 8; ++nt) {
            int rl = wm * 32 + mt * 16 + gid;       // local row in tile
            int r = row0 + rl;
            int cc = wn * 64 + nt * 8 + tig * 2;
            const float* a4 = acc[mt][nt];
            if (doRelu) {
                float2 p0 = *(const float2*)&sPts[rl * LDP + cc];
                float2 p1 = *(const float2*)&sPts[(rl + 8) * LDP + cc];
                *(float2*)&YaW[(size_t)r * C_ + cc] =
                    make_float2(p0.x + ALPHA_F * a4[0], p0.y + ALPHA_F * a4[1]);
                *(float2*)&YaW[(size_t)(r + 8) * C_ + cc] =
                    make_float2(p1.x + ALPHA_F * a4[2], p1.y + ALPHA_F * a4[3]);
            } else {
                *(float2*)&YgW[(size_t)r * C_ + cc]       = make_float2(a4[0], a4[1]);
                *(float2*)&YgW[(size_t)(r + 8) * C_ + cc] = make_float2(a4[2], a4[3]);
            }
        }
    }
}

// ------- 4) final gather: pts = Ya[p] + (1/72)*(sum_nbr Yg[p]) ---------------
__global__ void gather_combine(int par) {
    int node = blockIdx.x * 8 + (threadIdx.x >> 5);
    int lane = threadIdx.x & 31;
    int base = node & ~(N_ - 1);
    const int* nb = g_nbr + (size_t)node * KNN;
    int c = lane * 4;
    const float* YaR = g_Ya[par];
    const float* YgR = g_Yg[par];
    float4 acc = make_float4(0.f, 0.f, 0.f, 0.f);
#pragma unroll
    for (int s = 0; s < KNN; ++s) {
        const float4 v = *(const float4*)&YgR[(size_t)(base + nb[s]) * C_ + c];
        acc.x += v.x; acc.y += v.y; acc.z += v.z; acc.w += v.w;
    }
    float4 ya = *(const float4*)&YaR[(size_t)node * C_ + c];
    float4 o;
    o.x = ya.x + COEF_F * acc.x;
    o.y = ya.y + COEF_F * acc.y;
    o.z = ya.z + COEF_F * acc.z;
    o.w = ya.w + COEF_F * acc.w;
    *(float4*)&g_pts[(size_t)node * C_ + c] = o;
}

// ------- 5) unpool projection: Uc = pts@WucT, Ug = pts@WugT (6 outs each) ----
__global__ void unpool_proj(const float* __restrict__ Wuc,
                            const float* __restrict__ Wug) {
    __shared__ float swc[6 * C_], swg[6 * C_];
    for (int i = threadIdx.x; i < 6 * C_; i += 256) { swc[i] = Wuc[i]; swg[i] = Wug[i]; }
    __syncthreads();
    int node = blockIdx.x * 8 + (threadIdx.x >> 5);
    int lane = threadIdx.x & 31;
    float4 p = *(const float4*)&g_pts[(size_t)node * C_ + lane * 4];
#pragma unroll
    for (int o = 0; o < 6; ++o) {
        float4 wc = *(const float4*)&swc[o * C_ + lane * 4];
        float4 wg = *(const float4*)&swg[o * C_ + lane * 4];
        float dc = p.x * wc.x + p.y * wc.y + p.z * wc.z + p.w * wc.w;
        float dg = p.x * wg.x + p.y * wg.y + p.z * wg.z + p.w * wg.w;
#pragma unroll
        for (int off = 16; off; off >>= 1) {
            dc += __shfl_xor_sync(0xffffffffu, dc, off);
            dg += __shfl_xor_sync(0xffffffffu, dg, off);
        }
        if (lane == 0) {
            g_Uc[(size_t)node * 6 + o] = dc;
            g_Ug[(size_t)node * 6 + o] = dg;
        }
    }
}

// ------- 6) finalize new_xyz: a*Uc + (1-a)*(adj@Ug), fold + reshape ----------
__global__ void finalize_xyz(const float* __restrict__ xyz, float* __restrict__ out) {
    int node = blockIdx.x * 256 + threadIdx.x;
    int b = node >> 11, n = node & (N_ - 1);
    int base = node & ~(N_ - 1);
    const int* nb = g_nbr + (size_t)node * KNN;
    float g[6] = {0.f, 0.f, 0.f, 0.f, 0.f, 0.f};
#pragma unroll
    for (int s = 0; s < KNN; ++s) {
        const float* r = g_Ug + (size_t)(base + nb[s]) * 6;
#pragma unroll
        for (int o = 0; o < 6; ++o) g[o] += r[o];
    }
#pragma unroll
    for (int o = 0; o < 6; ++o) {
        float v = ALPHA_F * g_Uc[(size_t)node * 6 + o] + ONEMA_F * (WEDGE_F * g[o]);
        int cdim = o >> 1, t = o & 1;
        out[(size_t)b * 3 * (2 * N_) + cdim * (2 * N_) + t * N_ + n] =
            v + xyz[(size_t)b * 3 * N_ + cdim * N_ + n];
    }
}

// ------- 7) transpose pts (B,N,C) -> output (B,C,N) --------------------------
__global__ void transpose_out(float* __restrict__ out) {
    __shared__ float tile[32][33];
    int b = blockIdx.z;
    int n0 = blockIdx.x * 32, c0 = blockIdx.y * 32;
    const float* src = g_pts + (size_t)b * N_ * C_;
    float* dst = out + (size_t)b * C_ * N_;
    for (int r = threadIdx.y; r < 32; r += 8)
        tile[r][threadIdx.x] = src[(n0 + r) * C_ + c0 + threadIdx.x];
    __syncthreads();
    for (int r = threadIdx.y; r < 32; r += 8)
        dst[(c0 + r) * N_ + n0 + threadIdx.x] = tile[threadIdx.x][r];
}

// -----------------------------------------------------------------------------
extern "C" void kernel_launch(void* const* d_in, const int* in_sizes, int n_in,
                              void* d_out, int out_size) {
    const float* xyz    = (const float*)d_in[0];   // (16,3,2048)
    const float* points = (const float*)d_in[1];   // (16,128,2048)
    const float* Wc     = (const float*)d_in[2];   // (4,128,128)
    const float* Wg     = (const float*)d_in[3];   // (4,128,128)
    const float* Wuc    = (const float*)d_in[4];   // (6,128)
    const float* Wug    = (const float*)d_in[5];   // (6,128)
    float* out = (float*)d_out;                    // [new_xyz | pts_T] concatenated
    (void)in_sizes; (void)n_in; (void)out_size;

    // host-side config (idempotent; not a stream op)
    cudaFuncSetAttribute(gemm_tc, cudaFuncAttributeMaxDynamicSharedMemorySize,
                         GEMM_SMEM);

    // launches: 0 knn, 1 transpose_in, 2..5 gemm, 6 gather, 7 unpool,
    // 8 finalize, 9 transpose_out.  ncu -s 5 -> profiles gemm_tc(blk=3).
    knn_kernel<<<B_ * 8, 256>>>(xyz, Wc, Wg);
    transpose_in<<<dim3(N_ / 32, C_ / 32, B_), dim3(32, 8)>>>(points);
    for (int i = 0; i < NBLK; ++i) {
        // block i reads parity (i-1)&1 (ignored when fused=0), writes parity i&1
        gemm_tc<<<dim3(M_ / 128, 2), 256, GEMM_SMEM>>>(i, i > 0 ? 1 : 0,
                                                       (i + 1) & 1, i & 1);
    }
    gather_combine<<<M_ / 8, 256>>>((NBLK - 1) & 1);
    unpool_proj<<<M_ / 8, 256>>>(Wuc, Wug);
    finalize_xyz<<<M_ / 256, 256>>>(xyz, out);
    transpose_out<<<dim3(N_ / 32, C_ / 32, B_), dim3(32, 8)>>>(out + (size_t)B_ * 3 * 2 * N_);
}

// round 16
// speedup vs baseline: 1.8482x; 1.8482x over previous
#include <cuda_runtime.h>
#include <cuda_bf16.h>
#include <float.h>

// Problem constants
#define B_   16
#define N_   2048
#define C_   128
#define M_   (B_ * N_)          // 32768 rows
#define KNN  8
#define NBLK 4

#define ALPHA_F    0.8888888888888888f   // 8/9
#define ONEMA_F    0.1111111111111111f   // 1/9
#define WEDGE_F    0.125f                // normalized adjacency entry (deg=8 everywhere)
#define COEF_F     0.013888888888888888f // ONEMA*WEDGE = 1/72

typedef unsigned long long u64;
typedef unsigned int u32;

// ---------------- scratch (static device globals; no allocs allowed) ---------
__device__ float g_pts[M_ * C_];
__device__ float g_Ya [M_ * C_];   // pts + alpha * relu(pts)@WcT (residual fused)
__device__ float g_Yg [M_ * C_];
__device__ float g_Uc [M_ * 6];
__device__ float g_Ug [M_ * 6];
__device__ int   g_nbr[M_ * KNN];  // [0]=self, [1..7]=kNN (within-batch indices)
// precomputed bf16 splits of Wc/Wg: [mat][blk][128*128]
__device__ __nv_bfloat16 g_Wsh[2 * NBLK * C_ * C_];
__device__ __nv_bfloat16 g_Wsl[2 * NBLK * C_ * C_];

// ======================= helpers =============================================
__device__ __forceinline__ u32 smem_u32(const void* p) {
    u32 a;
    asm("{ .reg .u64 t; cvta.to.shared.u64 t, %1; cvt.u32.u64 %0, t; }"
        : "=r"(a) : "l"(p));
    return a;
}
__device__ __forceinline__ float bfhi(float x) {
    return __bfloat162float(__float2bfloat16_rn(x));
}
__device__ __forceinline__ u32 packbf(float lo, float hi) {
    u32 r; asm("cvt.rn.bf16x2.f32 %0, %1, %2;" : "=r"(r) : "f"(hi), "f"(lo));
    return r;
}
__device__ __forceinline__ void ldsm_x4(u32 r[4], u32 addr) {
    asm volatile("ldmatrix.sync.aligned.m8n8.x4.shared.b16 {%0,%1,%2,%3}, [%4];"
        : "=r"(r[0]), "=r"(r[1]), "=r"(r[2]), "=r"(r[3]) : "r"(addr));
}
__device__ __forceinline__ void mma16816(float c[4], const u32 a[4], const u32 b[2]) {
    asm volatile("mma.sync.aligned.m16n8k16.row.col.f32.bf16.bf16.f32 "
        "{%0,%1,%2,%3}, {%4,%5,%6,%7}, {%8,%9}, {%0,%1,%2,%3};"
        : "+f"(c[0]), "+f"(c[1]), "+f"(c[2]), "+f"(c[3])
        : "r"(a[0]), "r"(a[1]), "r"(a[2]), "r"(a[3]), "r"(b[0]), "r"(b[1]));
}

// HMMA smem layout (bf16, padded stride 136; 128-row A tile, 128-row W tile)
#define LDB  136
#define REG_BYTES (C_ * LDB * 2)          // 34816 per region
#define SM_AH 0
#define SM_AL REG_BYTES
#define SM_WH (2 * REG_BYTES)
#define SM_WL (3 * REG_BYTES)
#define GEMM_SMEM (4 * REG_BYTES)         // 139264 B

// ---------------- 1) kNN top-8 + Wc/Wg bf16 split prep -----------------------
__global__ void knn_kernel(const float* __restrict__ xyz,
                           const float* __restrict__ Wc,
                           const float* __restrict__ Wg) {
    __shared__ float4 sP[N_];   // (x, y, z, |p|^2) interleaved -> 1 LDS.128/cand
    {
        int gt = blockIdx.x * 256 + threadIdx.x;
        for (int i = gt; i < NBLK * C_ * C_; i += 128 * 256) {
            float w = Wc[i];
            float h = bfhi(w);
            g_Wsh[i] = __float2bfloat16_rn(h);
            g_Wsl[i] = __float2bfloat16_rn(w - h);
            float w2 = Wg[i];
            float h2 = bfhi(w2);
            g_Wsh[NBLK * C_ * C_ + i] = __float2bfloat16_rn(h2);
            g_Wsl[NBLK * C_ * C_ + i] = __float2bfloat16_rn(w2 - h2);
        }
    }
    int b = blockIdx.x >> 3;
    int qBase = (blockIdx.x & 7) * 256;
    const float* X = xyz + (size_t)b * 3 * N_;
    for (int i = threadIdx.x; i < N_; i += 256) {
        float x = X[i], y = X[N_ + i], z = X[2 * N_ + i];
        sP[i] = make_float4(x, y, z, x * x + y * y + z * z);
    }
    __syncthreads();

    int q = qBase + threadIdx.x;
    float4 qp = sP[q];
    float bd[KNN]; int bi[KNN];
#pragma unroll
    for (int s = 0; s < KNN; ++s) { bd[s] = FLT_MAX; bi[s] = 0x7fffffff; }

    for (int j = 0; j < N_; ++j) {
        float4 pj = sP[j];
        float inner = qp.x * pj.x + qp.y * pj.y + qp.z * pj.z;
        float d = (qp.w + pj.w) - 2.0f * inner;
        if (d < bd[KNN - 1]) {                   // strict <: stable tie (lower idx wins)
            bd[KNN - 1] = d; bi[KNN - 1] = j;
#pragma unroll
            for (int s = KNN - 1; s > 0; --s) {
                if (bd[s] < bd[s - 1]) {
                    float td = bd[s]; bd[s] = bd[s - 1]; bd[s - 1] = td;
                    int   ti = bi[s]; bi[s] = bi[s - 1]; bi[s - 1] = ti;
                }
            }
        }
    }
    int* outp = g_nbr + (size_t)(b * N_ + q) * KNN;
    outp[0] = q;
#pragma unroll
    for (int s = 1; s < KNN; ++s) outp[s] = bi[s];
}

// ------- 2) transpose points (B,C,N) -> pts (B,N,C) --------------------------
__global__ void transpose_in(const float* __restrict__ pin) {
    __shared__ float tile[32][33];
    int b = blockIdx.z;
    int n0 = blockIdx.x * 32, c0 = blockIdx.y * 32;
    const float* src = pin + (size_t)b * C_ * N_;
    float* dst = g_pts + (size_t)b * N_ * C_;
    for (int r = threadIdx.y; r < 32; r += 8)
        tile[r][threadIdx.x] = src[(c0 + r) * N_ + n0 + threadIdx.x];
    __syncthreads();
    for (int r = threadIdx.y; r < 32; r += 8)
        dst[(n0 + r) * C_ + c0 + threadIdx.x] = tile[threadIdx.x][r];
}

// ---------------- 3) HMMA GEMM (mma.sync bf16 3-split), stage-major order ----
// grid (256, 2). y=0: Ya = pts + ALPHA*(relu(pts)@WcT); y=1: Yg = pts@WgT.
// One CTA = 128x128 output tile, full K=128 in smem (1 CTA/SM, 8 warps).
// 8 warps as 4x2: warp (wm=wid&3, wn=wid>>2) owns rows wm*32..+31, cols wn*64..+63.
// MMA order stage-major (16x hh, 16x lh, 16x hl) so same-acc deps are ~16 apart.
__global__ __launch_bounds__(256) void gemm_tc(int blk) {
    extern __shared__ char S[];
    const int mat = blockIdx.y;               // 0 = Wc/relu path, 1 = Wg
    const bool doRelu = (mat == 0);
    int t = threadIdx.x;
    int row0 = blockIdx.x * 128;
    u32 sb = smem_u32(S);

    // ---- A tile: load f32, (relu), split-convert to bf16 hi/lo in smem ----
    {
        int row = t >> 1, half = t & 1;
        const float* src = &g_pts[(size_t)(row0 + row) * C_ + half * 64];
        u32 so = (u32)(row * LDB + half * 64) * 2;
#pragma unroll
        for (int j = 0; j < 16; ++j) {
            float4 v = *(const float4*)&src[j * 4];
            if (doRelu) {
                v.x = fmaxf(v.x, 0.f); v.y = fmaxf(v.y, 0.f);
                v.z = fmaxf(v.z, 0.f); v.w = fmaxf(v.w, 0.f);
            }
            float h0 = bfhi(v.x), h1 = bfhi(v.y), h2 = bfhi(v.z), h3 = bfhi(v.w);
            *(u64*)(S + SM_AH + so + j * 8) =
                (u64)packbf(h0, h1) | ((u64)packbf(h2, h3) << 32);
            *(u64*)(S + SM_AL + so + j * 8) =
                (u64)packbf(v.x - h0, v.y - h1) | ((u64)packbf(v.z - h2, v.w - h3) << 32);
        }
    }
    // ---- W tile: copy precomputed bf16 hi/lo into padded smem ----
    {
        int row = t >> 1, half = t & 1;
        size_t gb = (size_t)(mat * NBLK + blk) * (C_ * C_) + row * C_ + half * 64;
        const uint4* wh = (const uint4*)&g_Wsh[gb];
        const uint4* wl = (const uint4*)&g_Wsl[gb];
        u32 so = (u32)(row * LDB + half * 64) * 2;
#pragma unroll
        for (int j = 0; j < 8; ++j) {           // 64 bf16 = 128B = 8 uint4
            *(uint4*)(S + SM_WH + so + j * 16) = wh[j];
            *(uint4*)(S + SM_WL + so + j * 16) = wl[j];
        }
    }
    __syncthreads();

    int wid = t >> 5, lane = t & 31;
    int wm = wid & 3, wn = wid >> 2;
    int gid = lane >> 2, tig = lane & 3;

    int arow = (lane & 7) + ((lane >> 3) & 1) * 8;
    int acol = ((lane >> 4) & 1) * 8;
    int brow = (lane & 7) + ((lane >> 4) & 1) * 8;
    int bcol = ((lane >> 3) & 1) * 8;

    u32 aAh[2], aAl[2];
#pragma unroll
    for (int mt = 0; mt < 2; ++mt) {
        u32 o = (u32)((wm * 32 + mt * 16 + arow) * LDB + acol) * 2;
        aAh[mt] = sb + SM_AH + o;
        aAl[mt] = sb + SM_AL + o;
    }
    u32 aBh[4], aBl[4];
#pragma unroll
    for (int p = 0; p < 4; ++p) {
        u32 o = (u32)((wn * 64 + p * 16 + brow) * LDB + bcol) * 2;
        aBh[p] = sb + SM_WH + o;
        aBl[p] = sb + SM_WL + o;
    }

    float acc[2][8][4];
#pragma unroll
    for (int i = 0; i < 2; ++i)
#pragma unroll
        for (int j = 0; j < 8; ++j)
#pragma unroll
            for (int q = 0; q < 4; ++q) acc[i][j][q] = 0.f;

    for (int kt = 0; kt < 8; ++kt) {
        u32 kadd = kt * 32;                    // 16 bf16 cols = 32 bytes
        u32 ah0[4], ah1[4], al0[4], al1[4];
        ldsm_x4(ah0, aAh[0] + kadd); ldsm_x4(ah1, aAh[1] + kadd);
        ldsm_x4(al0, aAl[0] + kadd); ldsm_x4(al1, aAl[1] + kadd);
        u32 bh[4][4];
#pragma unroll
        for (int p = 0; p < 4; ++p) ldsm_x4(bh[p], aBh[p] + kadd);
        // stage hh: 16 MMAs, all-distinct accumulators
#pragma unroll
        for (int p = 0; p < 4; ++p) {
            mma16816(acc[0][2 * p],     ah0, bh[p]);
            mma16816(acc[0][2 * p + 1], ah0, bh[p] + 2);
            mma16816(acc[1][2 * p],     ah1, bh[p]);
            mma16816(acc[1][2 * p + 1], ah1, bh[p] + 2);
        }
        u32 bl[4][4];
#pragma unroll
        for (int p = 0; p < 4; ++p) ldsm_x4(bl[p], aBl[p] + kadd);
        // stage lh
#pragma unroll
        for (int p = 0; p < 4; ++p) {
            mma16816(acc[0][2 * p],     al0, bh[p]);
            mma16816(acc[0][2 * p + 1], al0, bh[p] + 2);
            mma16816(acc[1][2 * p],     al1, bh[p]);
            mma16816(acc[1][2 * p + 1], al1, bh[p] + 2);
        }
        // stage hl
#pragma unroll
        for (int p = 0; p < 4; ++p) {
            mma16816(acc[0][2 * p],     ah0, bl[p]);
            mma16816(acc[0][2 * p + 1], ah0, bl[p] + 2);
            mma16816(acc[1][2 * p],     ah1, bl[p]);
            mma16816(acc[1][2 * p + 1], ah1, bl[p] + 2);
        }
    }

    // ---- epilogue: c0,c1 -> (row, cc..+1); c2,c3 -> (row+8, cc..+1) ---------
#pragma unroll
    for (int mt = 0; mt < 2; ++mt) {
#pragma unroll
        for (int nt = 0; nt < 8; ++nt) {
            int r = row0 + wm * 32 + mt * 16 + gid;
            int cc = wn * 64 + nt * 8 + tig * 2;
            const float* a4 = acc[mt][nt];
            if (doRelu) {
                float2 p0 = *(const float2*)&g_pts[(size_t)r * C_ + cc];
                float2 p1 = *(const float2*)&g_pts[(size_t)(r + 8) * C_ + cc];
                *(float2*)&g_Ya[(size_t)r * C_ + cc] =
                    make_float2(p0.x + ALPHA_F * a4[0], p0.y + ALPHA_F * a4[1]);
                *(float2*)&g_Ya[(size_t)(r + 8) * C_ + cc] =
                    make_float2(p1.x + ALPHA_F * a4[2], p1.y + ALPHA_F * a4[3]);
            } else {
                *(float2*)&g_Yg[(size_t)r * C_ + cc]       = make_float2(a4[0], a4[1]);
                *(float2*)&g_Yg[(size_t)(r + 8) * C_ + cc] = make_float2(a4[2], a4[3]);
            }
        }
    }
}

// ------- 4) gather + residual: pts = Ya + (1/72)*(sum_nbr Yg) ----------------
__global__ void gather_combine() {
    int node = blockIdx.x * 8 + (threadIdx.x >> 5);
    int lane = threadIdx.x & 31;
    int base = node & ~(N_ - 1);                  // batch start row
    const int* nb = g_nbr + (size_t)node * KNN;
    int c = lane * 4;
    float4 acc = make_float4(0.f, 0.f, 0.f, 0.f);
#pragma unroll
    for (int s = 0; s < KNN; ++s) {
        const float4 v = *(const float4*)&g_Yg[(size_t)(base + nb[s]) * C_ + c];
        acc.x += v.x; acc.y += v.y; acc.z += v.z; acc.w += v.w;
    }
    float4 ya = *(const float4*)&g_Ya[(size_t)node * C_ + c];
    float4 o;
    o.x = ya.x + COEF_F * acc.x;
    o.y = ya.y + COEF_F * acc.y;
    o.z = ya.z + COEF_F * acc.z;
    o.w = ya.w + COEF_F * acc.w;
    *(float4*)&g_pts[(size_t)node * C_ + c] = o;
}

// ------- 5) unpool projection: Uc = pts@WucT, Ug = pts@WugT (6 outs each) ----
__global__ void unpool_proj(const float* __restrict__ Wuc,
                            const float* __restrict__ Wug) {
    __shared__ float swc[6 * C_], swg[6 * C_];
    for (int i = threadIdx.x; i < 6 * C_; i += 256) { swc[i] = Wuc[i]; swg[i] = Wug[i]; }
    __syncthreads();
    int node = blockIdx.x * 8 + (threadIdx.x >> 5);
    int lane = threadIdx.x & 31;
    float4 p = *(const float4*)&g_pts[(size_t)node * C_ + lane * 4];
#pragma unroll
    for (int o = 0; o < 6; ++o) {
        float4 wc = *(const float4*)&swc[o * C_ + lane * 4];
        float4 wg = *(const float4*)&swg[o * C_ + lane * 4];
        float dc = p.x * wc.x + p.y * wc.y + p.z * wc.z + p.w * wc.w;
        float dg = p.x * wg.x + p.y * wg.y + p.z * wg.z + p.w * wg.w;
#pragma unroll
        for (int off = 16; off; off >>= 1) {
            dc += __shfl_xor_sync(0xffffffffu, dc, off);
            dg += __shfl_xor_sync(0xffffffffu, dg, off);
        }
        if (lane == 0) {
            g_Uc[(size_t)node * 6 + o] = dc;
            g_Ug[(size_t)node * 6 + o] = dg;
        }
    }
}

// ------- 6) finalize new_xyz: a*Uc + (1-a)*(adj@Ug), fold + reshape ----------
__global__ void finalize_xyz(const float* __restrict__ xyz, float* __restrict__ out) {
    int node = blockIdx.x * 256 + threadIdx.x;
    int b = node >> 11, n = node & (N_ - 1);
    int base = node & ~(N_ - 1);
    const int* nb = g_nbr + (size_t)node * KNN;
    float g[6] = {0.f, 0.f, 0.f, 0.f, 0.f, 0.f};
#pragma unroll
    for (int s = 0; s < KNN; ++s) {
        const float* r = g_Ug + (size_t)(base + nb[s]) * 6;
#pragma unroll
        for (int o = 0; o < 6; ++o) g[o] += r[o];
    }
#pragma unroll
    for (int o = 0; o < 6; ++o) {
        float v = ALPHA_F * g_Uc[(size_t)node * 6 + o] + ONEMA_F * (WEDGE_F * g[o]);
        int cdim = o >> 1, t = o & 1;
        out[(size_t)b * 3 * (2 * N_) + cdim * (2 * N_) + t * N_ + n] =
            v + xyz[(size_t)b * 3 * N_ + cdim * N_ + n];
    }
}

// ------- 7) transpose pts (B,N,C) -> output (B,C,N) --------------------------
__global__ void transpose_out(float* __restrict__ out) {
    __shared__ float tile[32][33];
    int b = blockIdx.z;
    int n0 = blockIdx.x * 32, c0 = blockIdx.y * 32;
    const float* src = g_pts + (size_t)b * N_ * C_;
    float* dst = out + (size_t)b * C_ * N_;
    for (int r = threadIdx.y; r < 32; r += 8)
        tile[r][threadIdx.x] = src[(n0 + r) * C_ + c0 + threadIdx.x];
    __syncthreads();
    for (int r = threadIdx.y; r < 32; r += 8)
        dst[(c0 + r) * N_ + n0 + threadIdx.x] = tile[threadIdx.x][r];
}

// -----------------------------------------------------------------------------
extern "C" void kernel_launch(void* const* d_in, const int* in_sizes, int n_in,
                              void* d_out, int out_size) {
    const float* xyz    = (const float*)d_in[0];   // (16,3,2048)
    const float* points = (const float*)d_in[1];   // (16,128,2048)
    const float* Wc     = (const float*)d_in[2];   // (4,128,128)
    const float* Wg     = (const float*)d_in[3];   // (4,128,128)
    const float* Wuc    = (const float*)d_in[4];   // (6,128)
    const float* Wug    = (const float*)d_in[5];   // (6,128)
    float* out = (float*)d_out;                    // [new_xyz | pts_T] concatenated
    (void)in_sizes; (void)n_in; (void)out_size;

    // host-side config (idempotent; not a stream op)
    cudaFuncSetAttribute(gemm_tc, cudaFuncAttributeMaxDynamicSharedMemorySize,
                         GEMM_SMEM);

    // launches: 0 knn, 1 transpose_in, then 4x (gemm, gather), unpool,
    // finalize, transpose_out.
    knn_kernel<<<B_ * 8, 256>>>(xyz, Wc, Wg);
    transpose_in<<<dim3(N_ / 32, C_ / 32, B_), dim3(32, 8)>>>(points);
    for (int i = 0; i < NBLK; ++i) {
        gemm_tc<<<dim3(M_ / 128, 2), 256, GEMM_SMEM>>>(i);
        gather_combine<<<M_ / 8, 256>>>();
    }
    unpool_proj<<<M_ / 8, 256>>>(Wuc, Wug);
    finalize_xyz<<<M_ / 256, 256>>>(xyz, out);
    transpose_out<<<dim3(N_ / 32, C_ / 32, B_), dim3(32, 8)>>>(out + (size_t)B_ * 3 * 2 * N_);
}

// round 17
// speedup vs baseline: 1.9317x; 1.0452x over previous
#include <cuda_runtime.h>
#include <cuda_bf16.h>
#include <cuda_fp16.h>
#include <float.h>

// Problem constants
#define B_   16
#define N_   2048
#define C_   128
#define M_   (B_ * N_)          // 32768 rows
#define KNN  8
#define NBLK 4

#define ALPHA_F    0.8888888888888888f   // 8/9
#define ONEMA_F    0.1111111111111111f   // 1/9
#define WEDGE_F    0.125f                // normalized adjacency entry (deg=8 everywhere)
#define COEF_F     0.013888888888888888f // ONEMA*WEDGE = 1/72

typedef unsigned long long u64;
typedef unsigned int u32;

// ---------------- scratch (static device globals; no allocs allowed) ---------
__device__ float g_pts[M_ * C_];
__device__ float g_Ya [M_ * C_];   // pts + alpha * relu(pts)@WcT (residual fused)
__device__ float g_Yg [M_ * C_];
__device__ float g_Uc [M_ * 6];
__device__ float g_Ug [M_ * 6];
__device__ int   g_nbr[M_ * KNN];  // [0]=self, [1..7]=kNN (within-batch indices)
// precomputed splits: Wc -> bf16 hi/lo (3-split path); Wg -> fp16 hi (2-split path)
__device__ __nv_bfloat16 g_Wsh[NBLK * C_ * C_];
__device__ __nv_bfloat16 g_Wsl[NBLK * C_ * C_];
__device__ __half        g_Wgh[NBLK * C_ * C_];

// ======================= helpers =============================================
__device__ __forceinline__ u32 smem_u32(const void* p) {
    u32 a;
    asm("{ .reg .u64 t; cvta.to.shared.u64 t, %1; cvt.u32.u64 %0, t; }"
        : "=r"(a) : "l"(p));
    return a;
}
__device__ __forceinline__ float bfhi(float x) {
    return __bfloat162float(__float2bfloat16_rn(x));
}
__device__ __forceinline__ u32 packbf(float lo, float hi) {
    u32 r; asm("cvt.rn.bf16x2.f32 %0, %1, %2;" : "=r"(r) : "f"(hi), "f"(lo));
    return r;
}
__device__ __forceinline__ u32 packhf(float lo, float hi) {
    __half2 h = __floats2half2_rn(lo, hi);     // lo -> low half (lower address)
    return *(u32*)&h;
}
__device__ __forceinline__ void ldsm_x4(u32 r[4], u32 addr) {
    asm volatile("ldmatrix.sync.aligned.m8n8.x4.shared.b16 {%0,%1,%2,%3}, [%4];"
        : "=r"(r[0]), "=r"(r[1]), "=r"(r[2]), "=r"(r[3]) : "r"(addr));
}
__device__ __forceinline__ void mma16816(float c[4], const u32 a[4], const u32 b[2]) {
    asm volatile("mma.sync.aligned.m16n8k16.row.col.f32.bf16.bf16.f32 "
        "{%0,%1,%2,%3}, {%4,%5,%6,%7}, {%8,%9}, {%0,%1,%2,%3};"
        : "+f"(c[0]), "+f"(c[1]), "+f"(c[2]), "+f"(c[3])
        : "r"(a[0]), "r"(a[1]), "r"(a[2]), "r"(a[3]), "r"(b[0]), "r"(b[1]));
}
__device__ __forceinline__ void mma16816h(float c[4], const u32 a[4], const u32 b[2]) {
    asm volatile("mma.sync.aligned.m16n8k16.row.col.f32.f16.f16.f32 "
        "{%0,%1,%2,%3}, {%4,%5,%6,%7}, {%8,%9}, {%0,%1,%2,%3};"
        : "+f"(c[0]), "+f"(c[1]), "+f"(c[2]), "+f"(c[3])
        : "r"(a[0]), "r"(a[1]), "r"(a[2]), "r"(a[3]), "r"(b[0]), "r"(b[1]));
}

// HMMA smem layout (b16, padded stride 136; 128-row A tile, 128-row W tile)
#define LDB  136
#define REG_BYTES (C_ * LDB * 2)          // 34816 per region
#define SM_AH 0
#define SM_AL REG_BYTES
#define SM_WH (2 * REG_BYTES)
#define SM_WL (3 * REG_BYTES)
#define GEMM_SMEM (4 * REG_BYTES)         // 139264 B

// ---------------- 1) kNN top-8 + W split prep --------------------------------
__global__ void knn_kernel(const float* __restrict__ xyz,
                           const float* __restrict__ Wc,
                           const float* __restrict__ Wg) {
    __shared__ float4 sP[N_];   // (x, y, z, |p|^2) interleaved -> 1 LDS.128/cand
    {
        int gt = blockIdx.x * 256 + threadIdx.x;
        for (int i = gt; i < NBLK * C_ * C_; i += 128 * 256) {
            float w = Wc[i];
            float h = bfhi(w);
            g_Wsh[i] = __float2bfloat16_rn(h);
            g_Wsl[i] = __float2bfloat16_rn(w - h);
            g_Wgh[i] = __float2half_rn(Wg[i]);
        }
    }
    int b = blockIdx.x >> 3;
    int qBase = (blockIdx.x & 7) * 256;
    const float* X = xyz + (size_t)b * 3 * N_;
    for (int i = threadIdx.x; i < N_; i += 256) {
        float x = X[i], y = X[N_ + i], z = X[2 * N_ + i];
        sP[i] = make_float4(x, y, z, x * x + y * y + z * z);
    }
    __syncthreads();

    int q = qBase + threadIdx.x;
    float4 qp = sP[q];
    float bd[KNN]; int bi[KNN];
#pragma unroll
    for (int s = 0; s < KNN; ++s) { bd[s] = FLT_MAX; bi[s] = 0x7fffffff; }

    for (int j = 0; j < N_; ++j) {
        float4 pj = sP[j];
        float inner = qp.x * pj.x + qp.y * pj.y + qp.z * pj.z;
        float d = (qp.w + pj.w) - 2.0f * inner;
        if (d < bd[KNN - 1]) {                   // strict <: stable tie (lower idx wins)
            bd[KNN - 1] = d; bi[KNN - 1] = j;
#pragma unroll
            for (int s = KNN - 1; s > 0; --s) {
                if (bd[s] < bd[s - 1]) {
                    float td = bd[s]; bd[s] = bd[s - 1]; bd[s - 1] = td;
                    int   ti = bi[s]; bi[s] = bi[s - 1]; bi[s - 1] = ti;
                }
            }
        }
    }
    int* outp = g_nbr + (size_t)(b * N_ + q) * KNN;
    outp[0] = q;
#pragma unroll
    for (int s = 1; s < KNN; ++s) outp[s] = bi[s];
}

// ------- 2) transpose points (B,C,N) -> pts (B,N,C) --------------------------
__global__ void transpose_in(const float* __restrict__ pin) {
    __shared__ float tile[32][33];
    int b = blockIdx.z;
    int n0 = blockIdx.x * 32, c0 = blockIdx.y * 32;
    const float* src = pin + (size_t)b * C_ * N_;
    float* dst = g_pts + (size_t)b * N_ * C_;
    for (int r = threadIdx.y; r < 32; r += 8)
        tile[r][threadIdx.x] = src[(c0 + r) * N_ + n0 + threadIdx.x];
    __syncthreads();
    for (int r = threadIdx.y; r < 32; r += 8)
        dst[(n0 + r) * C_ + c0 + threadIdx.x] = tile[threadIdx.x][r];
}

// ---------------- 3) HMMA GEMM, mixed-precision splits -----------------------
// grid (256, 2).
//  y=0 (Yc): Ya = pts + ALPHA*(relu(pts)@WcT), bf16 3-split (hh+lh+hl),
//            interleaved MMA order (R8-verified).
//  y=1 (Yg): Yg = pts@WgT, fp16 2-split: (Ah+Al)@fp16(Wg) — exact A, W hi only.
//            Error = pts@(Wg - fp16(Wg)) ~1e-4, enters pts with weight 1/9.
// One CTA = 128x128 output tile, full K=128 in smem (1 CTA/SM, 8 warps).
// 8 warps as 4x2: warp (wm=wid&3, wn=wid>>2) owns rows wm*32..+31, cols wn*64..+63.
__global__ __launch_bounds__(256) void gemm_tc(int blk) {
    extern __shared__ char S[];
    const int mat = blockIdx.y;               // 0 = Wc/relu bf16x3, 1 = Wg fp16x2
    const bool doRelu = (mat == 0);
    int t = threadIdx.x;
    int row0 = blockIdx.x * 128;
    u32 sb = smem_u32(S);

    // ---- A tile: load f32, (relu), split-convert to hi/lo in smem ----------
    {
        int row = t >> 1, half = t & 1;
        const float* src = &g_pts[(size_t)(row0 + row) * C_ + half * 64];
        u32 so = (u32)(row * LDB + half * 64) * 2;
        if (doRelu) {
#pragma unroll
            for (int j = 0; j < 16; ++j) {
                float4 v = *(const float4*)&src[j * 4];
                v.x = fmaxf(v.x, 0.f); v.y = fmaxf(v.y, 0.f);
                v.z = fmaxf(v.z, 0.f); v.w = fmaxf(v.w, 0.f);
                float h0 = bfhi(v.x), h1 = bfhi(v.y), h2 = bfhi(v.z), h3 = bfhi(v.w);
                *(u64*)(S + SM_AH + so + j * 8) =
                    (u64)packbf(h0, h1) | ((u64)packbf(h2, h3) << 32);
                *(u64*)(S + SM_AL + so + j * 8) =
                    (u64)packbf(v.x - h0, v.y - h1) | ((u64)packbf(v.z - h2, v.w - h3) << 32);
            }
        } else {
#pragma unroll
            for (int j = 0; j < 16; ++j) {
                float4 v = *(const float4*)&src[j * 4];
                float h0 = __half2float(__float2half_rn(v.x));
                float h1 = __half2float(__float2half_rn(v.y));
                float h2 = __half2float(__float2half_rn(v.z));
                float h3 = __half2float(__float2half_rn(v.w));
                *(u64*)(S + SM_AH + so + j * 8) =
                    (u64)packhf(h0, h1) | ((u64)packhf(h2, h3) << 32);
                *(u64*)(S + SM_AL + so + j * 8) =
                    (u64)packhf(v.x - h0, v.y - h1) | ((u64)packhf(v.z - h2, v.w - h3) << 32);
            }
        }
    }
    // ---- W tile: copy precomputed splits into padded smem -------------------
    {
        int row = t >> 1, half = t & 1;
        size_t gb = (size_t)blk * (C_ * C_) + row * C_ + half * 64;
        u32 so = (u32)(row * LDB + half * 64) * 2;
        if (doRelu) {
            const uint4* wh = (const uint4*)&g_Wsh[gb];
            const uint4* wl = (const uint4*)&g_Wsl[gb];
#pragma unroll
            for (int j = 0; j < 8; ++j) {       // 64 b16 = 128B = 8 uint4
                *(uint4*)(S + SM_WH + so + j * 16) = wh[j];
                *(uint4*)(S + SM_WL + so + j * 16) = wl[j];
            }
        } else {
            const uint4* wh = (const uint4*)&g_Wgh[gb];
#pragma unroll
            for (int j = 0; j < 8; ++j)
                *(uint4*)(S + SM_WH + so + j * 16) = wh[j];
        }
    }
    __syncthreads();

    int wid = t >> 5, lane = t & 31;
    int wm = wid & 3, wn = wid >> 2;
    int gid = lane >> 2, tig = lane & 3;

    int arow = (lane & 7) + ((lane >> 3) & 1) * 8;
    int acol = ((lane >> 4) & 1) * 8;
    int brow = (lane & 7) + ((lane >> 4) & 1) * 8;
    int bcol = ((lane >> 3) & 1) * 8;

    u32 aAh[2], aAl[2];
#pragma unroll
    for (int mt = 0; mt < 2; ++mt) {
        u32 o = (u32)((wm * 32 + mt * 16 + arow) * LDB + acol) * 2;
        aAh[mt] = sb + SM_AH + o;
        aAl[mt] = sb + SM_AL + o;
    }
    u32 aBh[4], aBl[4];
#pragma unroll
    for (int p = 0; p < 4; ++p) {
        u32 o = (u32)((wn * 64 + p * 16 + brow) * LDB + bcol) * 2;
        aBh[p] = sb + SM_WH + o;
        aBl[p] = sb + SM_WL + o;
    }

    float acc[2][8][4];
#pragma unroll
    for (int i = 0; i < 2; ++i)
#pragma unroll
        for (int j = 0; j < 8; ++j)
#pragma unroll
            for (int q = 0; q < 4; ++q) acc[i][j][q] = 0.f;

    if (doRelu) {
        // ---- bf16 3-split, interleaved order (R8-verified) ------------------
        for (int kt = 0; kt < 8; ++kt) {
            u32 kadd = kt * 32;
            u32 ah0[4], ah1[4], al0[4], al1[4];
            ldsm_x4(ah0, aAh[0] + kadd); ldsm_x4(ah1, aAh[1] + kadd);
            ldsm_x4(al0, aAl[0] + kadd); ldsm_x4(al1, aAl[1] + kadd);
#pragma unroll
            for (int p = 0; p < 4; ++p) {
                u32 bh[4], bl[4];
                ldsm_x4(bh, aBh[p] + kadd);
                mma16816(acc[0][2 * p],     ah0, bh);
                mma16816(acc[0][2 * p + 1], ah0, bh + 2);
                mma16816(acc[1][2 * p],     ah1, bh);
                mma16816(acc[1][2 * p + 1], ah1, bh + 2);
                mma16816(acc[0][2 * p],     al0, bh);
                mma16816(acc[0][2 * p + 1], al0, bh + 2);
                mma16816(acc[1][2 * p],     al1, bh);
                mma16816(acc[1][2 * p + 1], al1, bh + 2);
                ldsm_x4(bl, aBl[p] + kadd);
                mma16816(acc[0][2 * p],     ah0, bl);
                mma16816(acc[0][2 * p + 1], ah0, bl + 2);
                mma16816(acc[1][2 * p],     ah1, bl);
                mma16816(acc[1][2 * p + 1], ah1, bl + 2);
            }
        }
    } else {
        // ---- fp16 2-split: (Ah+Al)@Wh ---------------------------------------
        for (int kt = 0; kt < 8; ++kt) {
            u32 kadd = kt * 32;
            u32 ah0[4], ah1[4], al0[4], al1[4];
            ldsm_x4(ah0, aAh[0] + kadd); ldsm_x4(ah1, aAh[1] + kadd);
            ldsm_x4(al0, aAl[0] + kadd); ldsm_x4(al1, aAl[1] + kadd);
#pragma unroll
            for (int p = 0; p < 4; ++p) {
                u32 bh[4];
                ldsm_x4(bh, aBh[p] + kadd);
                mma16816h(acc[0][2 * p],     ah0, bh);
                mma16816h(acc[0][2 * p + 1], ah0, bh + 2);
                mma16816h(acc[1][2 * p],     ah1, bh);
                mma16816h(acc[1][2 * p + 1], ah1, bh + 2);
                mma16816h(acc[0][2 * p],     al0, bh);
                mma16816h(acc[0][2 * p + 1], al0, bh + 2);
                mma16816h(acc[1][2 * p],     al1, bh);
                mma16816h(acc[1][2 * p + 1], al1, bh + 2);
            }
        }
    }

    // ---- epilogue: c0,c1 -> (row, cc..+1); c2,c3 -> (row+8, cc..+1) ---------
#pragma unroll
    for (int mt = 0; mt < 2; ++mt) {
#pragma unroll
        for (int nt = 0; nt < 8; ++nt) {
            int r = row0 + wm * 32 + mt * 16 + gid;
            int cc = wn * 64 + nt * 8 + tig * 2;
            const float* a4 = acc[mt][nt];
            if (doRelu) {
                float2 p0 = *(const float2*)&g_pts[(size_t)r * C_ + cc];
                float2 p1 = *(const float2*)&g_pts[(size_t)(r + 8) * C_ + cc];
                *(float2*)&g_Ya[(size_t)r * C_ + cc] =
                    make_float2(p0.x + ALPHA_F * a4[0], p0.y + ALPHA_F * a4[1]);
                *(float2*)&g_Ya[(size_t)(r + 8) * C_ + cc] =
                    make_float2(p1.x + ALPHA_F * a4[2], p1.y + ALPHA_F * a4[3]);
            } else {
                *(float2*)&g_Yg[(size_t)r * C_ + cc]       = make_float2(a4[0], a4[1]);
                *(float2*)&g_Yg[(size_t)(r + 8) * C_ + cc] = make_float2(a4[2], a4[3]);
            }
        }
    }
}

// ------- 4) gather + residual: pts = Ya + (1/72)*(sum_nbr Yg) ----------------
__global__ void gather_combine() {
    int node = blockIdx.x * 8 + (threadIdx.x >> 5);
    int lane = threadIdx.x & 31;
    int base = node & ~(N_ - 1);                  // batch start row
    const int* nb = g_nbr + (size_t)node * KNN;
    int c = lane * 4;
    float4 acc = make_float4(0.f, 0.f, 0.f, 0.f);
#pragma unroll
    for (int s = 0; s < KNN; ++s) {
        const float4 v = *(const float4*)&g_Yg[(size_t)(base + nb[s]) * C_ + c];
        acc.x += v.x; acc.y += v.y; acc.z += v.z; acc.w += v.w;
    }
    float4 ya = *(const float4*)&g_Ya[(size_t)node * C_ + c];
    float4 o;
    o.x = ya.x + COEF_F * acc.x;
    o.y = ya.y + COEF_F * acc.y;
    o.z = ya.z + COEF_F * acc.z;
    o.w = ya.w + COEF_F * acc.w;
    *(float4*)&g_pts[(size_t)node * C_ + c] = o;
}

// ------- 5) unpool projection: Uc = pts@WucT, Ug = pts@WugT (6 outs each) ----
__global__ void unpool_proj(const float* __restrict__ Wuc,
                            const float* __restrict__ Wug) {
    __shared__ float swc[6 * C_], swg[6 * C_];
    for (int i = threadIdx.x; i < 6 * C_; i += 256) { swc[i] = Wuc[i]; swg[i] = Wug[i]; }
    __syncthreads();
    int node = blockIdx.x * 8 + (threadIdx.x >> 5);
    int lane = threadIdx.x & 31;
    float4 p = *(const float4*)&g_pts[(size_t)node * C_ + lane * 4];
#pragma unroll
    for (int o = 0; o < 6; ++o) {
        float4 wc = *(const float4*)&swc[o * C_ + lane * 4];
        float4 wg = *(const float4*)&swg[o * C_ + lane * 4];
        float dc = p.x * wc.x + p.y * wc.y + p.z * wc.z + p.w * wc.w;
        float dg = p.x * wg.x + p.y * wg.y + p.z * wg.z + p.w * wg.w;
#pragma unroll
        for (int off = 16; off; off >>= 1) {
            dc += __shfl_xor_sync(0xffffffffu, dc, off);
            dg += __shfl_xor_sync(0xffffffffu, dg, off);
        }
        if (lane == 0) {
            g_Uc[(size_t)node * 6 + o] = dc;
            g_Ug[(size_t)node * 6 + o] = dg;
        }
    }
}

// ------- 6) finalize new_xyz: a*Uc + (1-a)*(adj@Ug), fold + reshape ----------
__global__ void finalize_xyz(const float* __restrict__ xyz, float* __restrict__ out) {
    int node = blockIdx.x * 256 + threadIdx.x;
    int b = node >> 11, n = node & (N_ - 1);
    int base = node & ~(N_ - 1);
    const int* nb = g_nbr + (size_t)node * KNN;
    float g[6] = {0.f, 0.f, 0.f, 0.f, 0.f, 0.f};
#pragma unroll
    for (int s = 0; s < KNN; ++s) {
        const float* r = g_Ug + (size_t)(base + nb[s]) * 6;
#pragma unroll
        for (int o = 0; o < 6; ++o) g[o] += r[o];
    }
#pragma unroll
    for (int o = 0; o < 6; ++o) {
        float v = ALPHA_F * g_Uc[(size_t)node * 6 + o] + ONEMA_F * (WEDGE_F * g[o]);
        int cdim = o >> 1, t = o & 1;
        out[(size_t)b * 3 * (2 * N_) + cdim * (2 * N_) + t * N_ + n] =
            v + xyz[(size_t)b * 3 * N_ + cdim * N_ + n];
    }
}

// ------- 7) transpose pts (B,N,C) -> output (B,C,N) --------------------------
__global__ void transpose_out(float* __restrict__ out) {
    __shared__ float tile[32][33];
    int b = blockIdx.z;
    int n0 = blockIdx.x * 32, c0 = blockIdx.y * 32;
    const float* src = g_pts + (size_t)b * N_ * C_;
    float* dst = out + (size_t)b * C_ * N_;
    for (int r = threadIdx.y; r < 32; r += 8)
        tile[r][threadIdx.x] = src[(n0 + r) * C_ + c0 + threadIdx.x];
    __syncthreads();
    for (int r = threadIdx.y; r < 32; r += 8)
        dst[(c0 + r) * N_ + n0 + threadIdx.x] = tile[threadIdx.x][r];
}

// -----------------------------------------------------------------------------
extern "C" void kernel_launch(void* const* d_in, const int* in_sizes, int n_in,
                              void* d_out, int out_size) {
    const float* xyz    = (const float*)d_in[0];   // (16,3,2048)
    const float* points = (const float*)d_in[1];   // (16,128,2048)
    const float* Wc     = (const float*)d_in[2];   // (4,128,128)
    const float* Wg     = (const float*)d_in[3];   // (4,128,128)
    const float* Wuc    = (const float*)d_in[4];   // (6,128)
    const float* Wug    = (const float*)d_in[5];   // (6,128)
    float* out = (float*)d_out;                    // [new_xyz | pts_T] concatenated
    (void)in_sizes; (void)n_in; (void)out_size;

    // host-side config (idempotent; not a stream op)
    cudaFuncSetAttribute(gemm_tc, cudaFuncAttributeMaxDynamicSharedMemorySize,
                         GEMM_SMEM);

    knn_kernel<<<B_ * 8, 256>>>(xyz, Wc, Wg);
    transpose_in<<<dim3(N_ / 32, C_ / 32, B_), dim3(32, 8)>>>(points);
    for (int i = 0; i < NBLK; ++i) {
        gemm_tc<<<dim3(M_ / 128, 2), 256, GEMM_SMEM>>>(i);
        gather_combine<<<M_ / 8, 256>>>();
    }
    unpool_proj<<<M_ / 8, 256>>>(Wuc, Wug);
    finalize_xyz<<<M_ / 256, 256>>>(xyz, out);
    transpose_out<<<dim3(N_ / 32, C_ / 32, B_), dim3(32, 8)>>>(out + (size_t)B_ * 3 * 2 * N_);
}